// round 11
// baseline (speedup 1.0000x reference)
#include <cuda_runtime.h>
#include <cuda_fp16.h>
#include <cstdint>

// Problem constants (fixed: x,y in f32[4,4096,128])
#define BATCH 4
#define NPTS  4096
#define DIM   128
#define NINF_BITS 0xff800000u   // -inf (acc-max formulation)

#define ROWB   256            // bytes per row in gmem (128 fp16)
#define SSTB   272            // smem row stride bytes (68 words, 68%32==4: ldmatrix conflict-free)

#define GRID_MAIN (BATCH * 64)  // 256 CTAs

// ---------------- global scratch (allocation-free rule) ----------------
__device__ __half  g_Ax[BATCH * NPTS * DIM];
__device__ __half  g_By[BATCH * NPTS * DIM];
__device__ float    g_x2[BATCH * NPTS];     // stores -x2/2
__device__ float    g_y2[BATCH * NPTS];     // stores -y2/2
__device__ unsigned g_rowmin[BATCH * NPTS]; // RED.MIN accumulated (clamped >=0)
__device__ unsigned g_colmin[BATCH * NPTS]; // RED.MIN accumulated (clamped >=0)
__device__ unsigned g_done;                 // completion counter (reset by hd_prep)

// ---------------- smem layout (bytes): M=128 tile, 2 CTAs/SM ----------------
#define A_OFF     0            // 128 * 272 = 34816
#define B0_OFF    34816
#define B1_OFF    69632
#define SMEM_BYTES 104448      // 2 CTAs x 102 KB fits the 227 KB carveout

// ---------------- PTX helpers (sm_80+ / plain sm_100-safe) ----------------
__device__ __forceinline__ uint32_t smem_u32(const void* p) {
    uint32_t a;
    asm("{ .reg .u64 t; cvta.to.shared.u64 t, %1; cvt.u32.u64 %0, t; }" : "=r"(a) : "l"(p));
    return a;
}
__device__ __forceinline__ void cp_async16(uint32_t saddr, const void* g) {
    asm volatile("cp.async.cg.shared.global [%0], [%1], 16;" :: "r"(saddr), "l"(g));
}
#define CP_COMMIT() asm volatile("cp.async.commit_group;" ::: "memory")
#define CP_WAIT0()  asm volatile("cp.async.wait_group 0;" ::: "memory")

__device__ __forceinline__ void ldsm_x4(uint32_t* r, uint32_t addr) {
    asm volatile("ldmatrix.sync.aligned.m8n8.x4.shared.b16 {%0,%1,%2,%3}, [%4];"
                 : "=r"(r[0]), "=r"(r[1]), "=r"(r[2]), "=r"(r[3]) : "r"(addr));
}
__device__ __forceinline__ void mma_f16(float* c, const uint32_t* a, const uint32_t* b) {
    asm volatile("mma.sync.aligned.m16n8k16.row.col.f32.f16.f16.f32 "
                 "{%0,%1,%2,%3}, {%4,%5,%6,%7}, {%8,%9}, {%0,%1,%2,%3};"
                 : "+f"(c[0]), "+f"(c[1]), "+f"(c[2]), "+f"(c[3])
                 : "r"(a[0]), "r"(a[1]), "r"(a[2]), "r"(a[3]), "r"(b[0]), "r"(b[1]));
}

// ---------------------------------------------------------------------------
// Kernel 1: fp16 convert + (-0.5 * squared norm) + min-array + counter init.
// Half-warp per row; consecutive float4 loads -> single 16B store per lane.
// ---------------------------------------------------------------------------
__global__ void hd_prep(const float* __restrict__ x, const float* __restrict__ y) {
    int gtid = blockIdx.x * blockDim.x + threadIdx.x;
    if (gtid < BATCH * NPTS) {
        g_colmin[gtid] = 0x7f800000u;   // +inf
        g_rowmin[gtid] = 0x7f800000u;
    }
    if (gtid == 0) g_done = 0;

    int hw   = gtid >> 4;
    int hl   = gtid & 15;
    bool isx = hw < BATCH * NPTS;
    int row  = isx ? hw : hw - BATCH * NPTS;
    const float* src = (isx ? x : y) + (size_t)row * DIM;

    float4 v0 = ((const float4*)src)[2 * hl];
    float4 v1 = ((const float4*)src)[2 * hl + 1];

    __half2 a0 = __floats2half2_rn(v0.x, v0.y);
    __half2 a1 = __floats2half2_rn(v0.z, v0.w);
    __half2 b0 = __floats2half2_rn(v1.x, v1.y);
    __half2 b1 = __floats2half2_rn(v1.z, v1.w);
    uint4 pk;
    pk.x = *(unsigned*)&a0; pk.y = *(unsigned*)&a1;
    pk.z = *(unsigned*)&b0; pk.w = *(unsigned*)&b1;

    __half* dst = (isx ? g_Ax : g_By) + (size_t)row * DIM;
    ((uint4*)dst)[hl] = pk;

    float s = v0.x * v0.x + v0.y * v0.y + v0.z * v0.z + v0.w * v0.w
            + v1.x * v1.x + v1.y * v1.y + v1.z * v1.z + v1.w * v1.w;
    #pragma unroll
    for (int o = 8; o > 0; o >>= 1) s += __shfl_xor_sync(0xffffffffu, s, o);
    if (hl == 0) {
        float h = -0.5f * s;
        if (isx) g_x2[row] = h;
        else     g_y2[row] = h;
    }
}

// ---------------------------------------------------------------------------
// Kernel 2: fp16 mma.sync GEMM with ACC-PRELOADED min epilogue + fused
// finalize (last CTA reduces rowmin/colmin -> out).
// acc initialized to -(x2+y2)/2, so acc_final = -d2/2 and min(d2) == max(acc):
// per-element epilogue is 2 FMAX; -2 scale + clamp at flush.
// M-tile = 128 rows of x; 32 m-tiles of y split across 2 CTAs (16 each) ->
// grid 256, 2 CTAs/SM. B prefetch interleaved into the k-loop; hy prefetched
// one tile ahead; B frags via ldsm_x4.
// ---------------------------------------------------------------------------
extern __shared__ unsigned char smem_raw[];

__global__ __launch_bounds__(256, 2)
void hd_main(float* __restrict__ out) {
    unsigned char* sm = smem_raw;
    const uint32_t sbase = smem_u32(sm);
    const int tid  = threadIdx.x;
    const int wid  = tid >> 5;
    const int ln   = tid & 31;
    const int wm   = wid >> 2;       // 0..1  (M half: 64 rows)
    const int wn   = wid & 3;        // 0..3  (N quarter: 32 cols)
    const int half = blockIdx.x & 1;
    const int nt   = (blockIdx.x >> 1) & 31;
    const int b    = blockIdx.x >> 6;
    const int n0   = nt * 128;
    const int t0   = half * 16;

    const int prow = tid >> 4;          // base row for fills
    const int pcol = tid & 15;          // 16B chunk within row

    // ---- prologue: async-load A tile and B tile t0 ----
    {
        const unsigned char* asrc = (const unsigned char*)(g_Ax + (size_t)(b * NPTS + n0) * DIM);
        const unsigned char* bsrc = (const unsigned char*)(g_By + (size_t)(b * NPTS + t0 * 128) * DIM);
        #pragma unroll
        for (int it = 0; it < 8; it++) {
            int row = prow + it * 16;
            cp_async16(sbase + A_OFF  + row * SSTB + pcol * 16, asrc + (size_t)row * ROWB + pcol * 16);
            cp_async16(sbase + B0_OFF + row * SSTB + pcol * 16, bsrc + (size_t)row * ROWB + pcol * 16);
        }
        CP_COMMIT();
        CP_WAIT0();
    }
    __syncthreads();

    // hx = -x2/2 per thread: 8 rows (mi 0..3, k2 0..1)
    float hx[4][2];
    #pragma unroll
    for (int mi = 0; mi < 4; mi++)
        #pragma unroll
        for (int k2 = 0; k2 < 2; k2++)
            hx[mi][k2] = g_x2[b * NPTS + n0 + wm * 64 + mi * 16 + (ln >> 2) + k2 * 8];

    // hy = -y2/2 for tile t0 (prefetched one tile ahead inside the loop)
    float hy[4][2];
    #pragma unroll
    for (int ni = 0; ni < 4; ni++)
        #pragma unroll
        for (int e = 0; e < 2; e++)
            hy[ni][e] = g_y2[b * NPTS + t0 * 128 + wn * 32 + ni * 8 + (ln & 3) * 2 + e];

    // ldmatrix base addresses (k-step adds 32 B each)
    uint32_t aaddr[4], baddr[2];
    #pragma unroll
    for (int mi = 0; mi < 4; mi++)
        aaddr[mi] = sbase + A_OFF + (wm * 64 + mi * 16 + (ln & 15)) * SSTB + (ln >> 4) * 16;
    // B via ldsm_x4: matrices [ni-even k-lo][ni-even k-hi][ni-odd k-lo][ni-odd k-hi]
    #pragma unroll
    for (int pr = 0; pr < 2; pr++)
        baddr[pr] = sbase + B0_OFF +
                    (wn * 32 + pr * 16 + ((ln >> 4) & 1) * 8 + (ln & 7)) * SSTB +
                    ((ln >> 3) & 1) * 16;

    float rm[8];   // running MAX of acc per row slot (mi*2+k2)
    #pragma unroll
    for (int r = 0; r < 8; r++) rm[r] = __uint_as_float(NINF_BITS);

    for (int t = t0; t < t0 + 16; t++) {
        const bool pf = (t < t0 + 15);
        const unsigned char* nbsrc =
            (const unsigned char*)(g_By + (size_t)(b * NPTS + (t + 1) * 128) * DIM);
        const uint32_t nboff = sbase + (((t + 1) & 1) ? B1_OFF : B0_OFF);
        const uint32_t bsel  = (t & 1) ? (B1_OFF - B0_OFF) : 0u;

        // acc preload: -(x2+y2)/2
        float acc[4][4][4];
        #pragma unroll
        for (int mi = 0; mi < 4; mi++)
            #pragma unroll
            for (int ni = 0; ni < 4; ni++)
                #pragma unroll
                for (int k = 0; k < 4; k++)
                    acc[mi][ni][k] = hx[mi][k >> 1] + hy[ni][k & 1];

        // prefetch hy for tile t+1 (lands during this tile's mainloop)
        {
            int tn = pf ? (t + 1) : t0;   // harmless in-range addr on last tile
            #pragma unroll
            for (int ni = 0; ni < 4; ni++)
                #pragma unroll
                for (int e = 0; e < 2; e++)
                    hy[ni][e] = g_y2[b * NPTS + tn * 128 + wn * 32 + ni * 8 + (ln & 3) * 2 + e];
        }

        // ---- mainloop: K=128 in 8 k-steps; 1 B-prefetch chunk per thread/ks ----
        #pragma unroll
        for (int ks = 0; ks < 8; ks++) {
            if (pf) {
                int row = prow + ks * 16;
                cp_async16(nboff + row * SSTB + pcol * 16,
                           nbsrc + (size_t)row * ROWB + pcol * 16);
            }
            uint32_t afr[4][4], bq[2][4];
            #pragma unroll
            for (int mi = 0; mi < 4; mi++) ldsm_x4(afr[mi], aaddr[mi] + ks * 32);
            #pragma unroll
            for (int pr = 0; pr < 2; pr++) ldsm_x4(bq[pr], baddr[pr] + bsel + ks * 32);
            #pragma unroll
            for (int mi = 0; mi < 4; mi++)
                #pragma unroll
                for (int ni = 0; ni < 4; ni++)
                    mma_f16(acc[mi][ni], afr[mi], &bq[ni >> 1][(ni & 1) * 2]);
        }
        if (pf) CP_COMMIT();

        // ---- epilogue: 2 FMAX per element ----
        float cmv[4][2];
        #pragma unroll
        for (int ni = 0; ni < 4; ni++)
            #pragma unroll
            for (int e = 0; e < 2; e++) cmv[ni][e] = __uint_as_float(NINF_BITS);

        #pragma unroll
        for (int mi = 0; mi < 4; mi++)
            #pragma unroll
            for (int ni = 0; ni < 4; ni++)
                #pragma unroll
                for (int k = 0; k < 4; k++) {
                    float a = acc[mi][ni][k];
                    rm[mi * 2 + (k >> 1)] = fmaxf(rm[mi * 2 + (k >> 1)], a);
                    cmv[ni][k & 1]        = fmaxf(cmv[ni][k & 1], a);
                }

        if (pf) CP_WAIT0();   // this thread's prefetch chunks landed
        __syncthreads();      // everyone done reading old buffer before overwrite

        // colmin flush AFTER the barrier: shfl-max + fire-and-forget RED.MIN
        #pragma unroll
        for (int ni = 0; ni < 4; ni++)
            #pragma unroll
            for (int e = 0; e < 2; e++) {
                float v = cmv[ni][e];
                v = fmaxf(v, __shfl_xor_sync(0xffffffffu, v, 4));
                v = fmaxf(v, __shfl_xor_sync(0xffffffffu, v, 8));
                v = fmaxf(v, __shfl_xor_sync(0xffffffffu, v, 16));
                if (ln < 4) {
                    float d2 = fmaxf(-2.0f * v, 0.0f);
                    atomicMin(&g_colmin[b * NPTS + t * 128 + wn * 32 + ni * 8 + ln * 2 + e],
                              __float_as_uint(d2));
                }
            }
    }

    // ---- final rowmin: fold cols across lanes, scale, clamp, RED.MIN ----
    #pragma unroll
    for (int r = 0; r < 8; r++) {
        float v = rm[r];
        v = fmaxf(v, __shfl_xor_sync(0xffffffffu, v, 1));
        v = fmaxf(v, __shfl_xor_sync(0xffffffffu, v, 2));
        if ((ln & 3) == 0) {
            int row = wm * 64 + (r >> 1) * 16 + (ln >> 2) + (r & 1) * 8;
            float d2 = fmaxf(-2.0f * v, 0.0f);
            atomicMin(&g_rowmin[b * NPTS + n0 + row], __float_as_uint(d2));
        }
    }

    // ---- fused finalize: last CTA reduces everything ----
    __threadfence();                       // make our REDs visible
    __shared__ unsigned s_last;
    __shared__ float s_red[256];
    if (tid == 0) s_last = (atomicAdd(&g_done, 1u) == GRID_MAIN - 1u) ? 1u : 0u;
    __syncthreads();
    if (s_last) {
        // all other CTAs' REDs are fenced-before-counter -> visible here
        float sum = 0.0f;
        for (int bb = 0; bb < BATCH; bb++) {
            float mx = 0.0f;
            for (int i = tid; i < NPTS; i += 256) {
                mx = fmaxf(mx, __uint_as_float(g_rowmin[bb * NPTS + i]));
                mx = fmaxf(mx, __uint_as_float(g_colmin[bb * NPTS + i]));
            }
            s_red[tid] = mx;
            __syncthreads();
            for (int st = 128; st > 0; st >>= 1) {
                if (tid < st) s_red[tid] = fmaxf(s_red[tid], s_red[tid + st]);
                __syncthreads();
            }
            if (tid == 0) sum += sqrtf(s_red[0]);
            __syncthreads();
        }
        if (tid == 0) out[0] = sum * (1.0f / BATCH);
    }
}

// ---------------------------------------------------------------------------
extern "C" void kernel_launch(void* const* d_in, const int* in_sizes, int n_in,
                              void* d_out, int out_size) {
    const float* x = (const float*)d_in[0];
    const float* y = (const float*)d_in[1];
    float* out = (float*)d_out;

    (void)cudaFuncSetAttribute(hd_main, cudaFuncAttributeMaxDynamicSharedMemorySize,
                               SMEM_BYTES);

    hd_prep<<<2048, 256>>>(x, y);
    hd_main<<<GRID_MAIN, 256, SMEM_BYTES>>>(out);
}

// round 12
// speedup vs baseline: 1.0515x; 1.0515x over previous
#include <cuda_runtime.h>
#include <cuda_fp16.h>
#include <cstdint>

// Problem constants (fixed: x,y in f32[4,4096,128])
#define BATCH 4
#define NPTS  4096
#define DIM   128
#define NINF_BITS 0xff800000u   // -inf (acc-max formulation)

#define ROWB   256            // bytes per row in gmem (128 fp16)
#define SSTB   272            // smem row stride bytes (68 words, 68%32==4: ldmatrix conflict-free)

#define GRID_MAIN (BATCH * 64)  // 256 CTAs

// ---------------- global scratch (allocation-free rule) ----------------
__device__ __half  g_Ax[BATCH * NPTS * DIM];
__device__ __half  g_By[BATCH * NPTS * DIM];
__device__ float    g_x2[BATCH * NPTS];     // stores -x2/2
__device__ float    g_y2[BATCH * NPTS];     // stores -y2/2
__device__ unsigned g_rowmin[BATCH * NPTS]; // RED.MIN accumulated (clamped >=0)
__device__ unsigned g_colmin[BATCH * NPTS]; // RED.MIN accumulated (clamped >=0)
__device__ unsigned g_done;                 // completion counter (reset by hd_prep)

// ---------------- smem layout (bytes): 110.5 KB/CTA, 2 CTAs/SM ----------------
#define A_OFF     0            // 128 * 272 = 34816
#define B0_OFF    34816
#define B1_OFF    69632
#define S_HX_OFF  104448       // 128 floats (-x2/2 for this CTA's rows)
#define S_HY_OFF  104960       // 2048 floats (-y2/2 for this CTA's 16 m-tiles)
#define SMEM_BYTES 113152

// ---------------- PTX helpers (sm_80+ / plain sm_100-safe) ----------------
__device__ __forceinline__ uint32_t smem_u32(const void* p) {
    uint32_t a;
    asm("{ .reg .u64 t; cvta.to.shared.u64 t, %1; cvt.u32.u64 %0, t; }" : "=r"(a) : "l"(p));
    return a;
}
__device__ __forceinline__ void cp_async16(uint32_t saddr, const void* g) {
    asm volatile("cp.async.cg.shared.global [%0], [%1], 16;" :: "r"(saddr), "l"(g));
}
#define CP_COMMIT() asm volatile("cp.async.commit_group;" ::: "memory")
#define CP_WAIT0()  asm volatile("cp.async.wait_group 0;" ::: "memory")

__device__ __forceinline__ void ldsm_x4(uint32_t* r, uint32_t addr) {
    asm volatile("ldmatrix.sync.aligned.m8n8.x4.shared.b16 {%0,%1,%2,%3}, [%4];"
                 : "=r"(r[0]), "=r"(r[1]), "=r"(r[2]), "=r"(r[3]) : "r"(addr));
}
__device__ __forceinline__ void mma_f16(float* c, const uint32_t* a, const uint32_t* b) {
    asm volatile("mma.sync.aligned.m16n8k16.row.col.f32.f16.f16.f32 "
                 "{%0,%1,%2,%3}, {%4,%5,%6,%7}, {%8,%9}, {%0,%1,%2,%3};"
                 : "+f"(c[0]), "+f"(c[1]), "+f"(c[2]), "+f"(c[3])
                 : "r"(a[0]), "r"(a[1]), "r"(a[2]), "r"(a[3]), "r"(b[0]), "r"(b[1]));
}

// ---------------------------------------------------------------------------
// Kernel 1: fp16 convert + (-0.5 * squared norm) + min-array + counter init.
// Quarter-warp (8 lanes) per row: 4 consecutive LDG.128 per thread (MLP=4),
// 2 contiguous 16B stores, 3-level shfl reduce.
// ---------------------------------------------------------------------------
__global__ void hd_prep(const float* __restrict__ x, const float* __restrict__ y) {
    int gtid = blockIdx.x * blockDim.x + threadIdx.x;
    if (gtid < BATCH * NPTS) {
        g_colmin[gtid] = 0x7f800000u;   // +inf
        g_rowmin[gtid] = 0x7f800000u;
    }
    if (gtid == 0) g_done = 0;

    int qw   = gtid >> 3;          // quarter-warp index = row over both tensors
    int hl   = gtid & 7;
    bool isx = qw < BATCH * NPTS;
    int row  = isx ? qw : qw - BATCH * NPTS;
    const float* src = (isx ? x : y) + (size_t)row * DIM;

    float4 v0 = ((const float4*)src)[4 * hl];
    float4 v1 = ((const float4*)src)[4 * hl + 1];
    float4 v2 = ((const float4*)src)[4 * hl + 2];
    float4 v3 = ((const float4*)src)[4 * hl + 3];

    __half2 c0 = __floats2half2_rn(v0.x, v0.y), c1 = __floats2half2_rn(v0.z, v0.w);
    __half2 c2 = __floats2half2_rn(v1.x, v1.y), c3 = __floats2half2_rn(v1.z, v1.w);
    __half2 c4 = __floats2half2_rn(v2.x, v2.y), c5 = __floats2half2_rn(v2.z, v2.w);
    __half2 c6 = __floats2half2_rn(v3.x, v3.y), c7 = __floats2half2_rn(v3.z, v3.w);
    uint4 p0, p1;
    p0.x = *(unsigned*)&c0; p0.y = *(unsigned*)&c1;
    p0.z = *(unsigned*)&c2; p0.w = *(unsigned*)&c3;
    p1.x = *(unsigned*)&c4; p1.y = *(unsigned*)&c5;
    p1.z = *(unsigned*)&c6; p1.w = *(unsigned*)&c7;

    __half* dst = (isx ? g_Ax : g_By) + (size_t)row * DIM;
    ((uint4*)dst)[2 * hl]     = p0;
    ((uint4*)dst)[2 * hl + 1] = p1;

    float s = v0.x * v0.x + v0.y * v0.y + v0.z * v0.z + v0.w * v0.w
            + v1.x * v1.x + v1.y * v1.y + v1.z * v1.z + v1.w * v1.w
            + v2.x * v2.x + v2.y * v2.y + v2.z * v2.z + v2.w * v2.w
            + v3.x * v3.x + v3.y * v3.y + v3.z * v3.z + v3.w * v3.w;
    #pragma unroll
    for (int o = 4; o > 0; o >>= 1) s += __shfl_xor_sync(0xffffffffu, s, o);
    if (hl == 0) {
        float h = -0.5f * s;
        if (isx) g_x2[row] = h;
        else     g_y2[row] = h;
    }
}

// ---------------------------------------------------------------------------
// Kernel 2: fp16 mma.sync GEMM, acc preloaded with -(x2+y2)/2 (min(d2) ==
// max(acc); epilogue = 2 FMAX/elem), fused last-CTA finalize.
// A fragments DOUBLE-BUFFERED across k-steps (A is t-invariant, so the ks=7
// slot preloads ks=0 for the next tile -> steady-state fragment pipeline).
// hx/hy live in smem (loaded once in the prologue) to free the registers the
// pipeline needs. M-tile = 128 rows of x; 32 m-tiles of y split across 2
// CTAs (16 each) -> grid 256, 2 CTAs/SM. B gmem prefetch interleaved 1 chunk
// per thread per k-step.
// ---------------------------------------------------------------------------
extern __shared__ unsigned char smem_raw[];

__global__ __launch_bounds__(256, 2)
void hd_main(float* __restrict__ out) {
    unsigned char* sm = smem_raw;
    const uint32_t sbase = smem_u32(sm);
    const int tid  = threadIdx.x;
    const int wid  = tid >> 5;
    const int ln   = tid & 31;
    const int wm   = wid >> 2;       // 0..1  (M half: 64 rows)
    const int wn   = wid & 3;        // 0..3  (N quarter: 32 cols)
    const int half = blockIdx.x & 1;
    const int nt   = (blockIdx.x >> 1) & 31;
    const int b    = blockIdx.x >> 6;
    const int n0   = nt * 128;
    const int t0   = half * 16;

    const int prow = tid >> 4;          // base row for fills
    const int pcol = tid & 15;          // 16B chunk within row

    float* s_hx = (float*)(sm + S_HX_OFF);
    float* s_hy = (float*)(sm + S_HY_OFF);

    // ---- prologue: async-load A tile + B tile t0; stage hx/hy into smem ----
    {
        const unsigned char* asrc = (const unsigned char*)(g_Ax + (size_t)(b * NPTS + n0) * DIM);
        const unsigned char* bsrc = (const unsigned char*)(g_By + (size_t)(b * NPTS + t0 * 128) * DIM);
        #pragma unroll
        for (int it = 0; it < 8; it++) {
            int row = prow + it * 16;
            cp_async16(sbase + A_OFF  + row * SSTB + pcol * 16, asrc + (size_t)row * ROWB + pcol * 16);
            cp_async16(sbase + B0_OFF + row * SSTB + pcol * 16, bsrc + (size_t)row * ROWB + pcol * 16);
        }
        CP_COMMIT();
        if (tid < 128) s_hx[tid] = g_x2[b * NPTS + n0 + tid];
        const float4* ysrc = (const float4*)(g_y2 + b * NPTS + t0 * 128);
        ((float4*)s_hy)[2 * tid]     = ysrc[2 * tid];
        ((float4*)s_hy)[2 * tid + 1] = ysrc[2 * tid + 1];
        CP_WAIT0();
    }
    __syncthreads();

    // ldmatrix base addresses (k-step adds 32 B each)
    uint32_t aaddr[4], baddr[2];
    #pragma unroll
    for (int mi = 0; mi < 4; mi++)
        aaddr[mi] = sbase + A_OFF + (wm * 64 + mi * 16 + (ln & 15)) * SSTB + (ln >> 4) * 16;
    #pragma unroll
    for (int pr = 0; pr < 2; pr++)
        baddr[pr] = sbase + B0_OFF +
                    (wn * 32 + pr * 16 + ((ln >> 4) & 1) * 8 + (ln & 7)) * SSTB +
                    ((ln >> 3) & 1) * 16;

    // A fragment double buffer; preload ks=0 into buf 0 (t-invariant)
    uint32_t afr[2][4][4];
    #pragma unroll
    for (int mi = 0; mi < 4; mi++) ldsm_x4(afr[0][mi], aaddr[mi]);

    float rm[8];   // running MAX of acc per row slot (mi*2+k2)
    #pragma unroll
    for (int r = 0; r < 8; r++) rm[r] = __uint_as_float(NINF_BITS);

    for (int t = t0; t < t0 + 16; t++) {
        const bool pf = (t < t0 + 15);
        const unsigned char* nbsrc =
            (const unsigned char*)(g_By + (size_t)(b * NPTS + (t + 1) * 128) * DIM);
        const uint32_t nboff = sbase + (((t + 1) & 1) ? B1_OFF : B0_OFF);
        const uint32_t bsel  = (t & 1) ? (B1_OFF - B0_OFF) : 0u;

        // acc preload: -(x2+y2)/2 from smem (short-lived temps)
        float acc[4][4][4];
        {
            float hxv[4][2], hyv[4][2];
            #pragma unroll
            for (int mi = 0; mi < 4; mi++)
                #pragma unroll
                for (int k2 = 0; k2 < 2; k2++)
                    hxv[mi][k2] = s_hx[wm * 64 + mi * 16 + (ln >> 2) + k2 * 8];
            #pragma unroll
            for (int ni = 0; ni < 4; ni++)
                #pragma unroll
                for (int e = 0; e < 2; e++)
                    hyv[ni][e] = s_hy[(t - t0) * 128 + wn * 32 + ni * 8 + (ln & 3) * 2 + e];
            #pragma unroll
            for (int mi = 0; mi < 4; mi++)
                #pragma unroll
                for (int ni = 0; ni < 4; ni++)
                    #pragma unroll
                    for (int k = 0; k < 4; k++)
                        acc[mi][ni][k] = hxv[mi][k >> 1] + hyv[ni][k & 1];
        }

        // ---- mainloop: K=128 in 8 k-steps; A frags pipelined one step ahead ----
        #pragma unroll
        for (int ks = 0; ks < 8; ks++) {
            if (pf) {   // 1 gmem->smem prefetch chunk per thread per ks
                int row = prow + ks * 16;
                cp_async16(nboff + row * SSTB + pcol * 16,
                           nbsrc + (size_t)row * ROWB + pcol * 16);
            }
            uint32_t bq[2][4];
            #pragma unroll
            for (int pr = 0; pr < 2; pr++) ldsm_x4(bq[pr], baddr[pr] + bsel + ks * 32);
            // A for next k-step (ks=7 reloads ks=0: same data every tile)
            const int nks = (ks + 1) & 7;
            #pragma unroll
            for (int mi = 0; mi < 4; mi++) ldsm_x4(afr[nks & 1][mi], aaddr[mi] + nks * 32);
            #pragma unroll
            for (int mi = 0; mi < 4; mi++)
                #pragma unroll
                for (int ni = 0; ni < 4; ni++)
                    mma_f16(acc[mi][ni], afr[ks & 1][mi], &bq[ni >> 1][(ni & 1) * 2]);
        }
        if (pf) CP_COMMIT();

        // ---- epilogue: 2 FMAX per element ----
        float cmv[4][2];
        #pragma unroll
        for (int ni = 0; ni < 4; ni++)
            #pragma unroll
            for (int e = 0; e < 2; e++) cmv[ni][e] = __uint_as_float(NINF_BITS);

        #pragma unroll
        for (int mi = 0; mi < 4; mi++)
            #pragma unroll
            for (int ni = 0; ni < 4; ni++)
                #pragma unroll
                for (int k = 0; k < 4; k++) {
                    float a = acc[mi][ni][k];
                    rm[mi * 2 + (k >> 1)] = fmaxf(rm[mi * 2 + (k >> 1)], a);
                    cmv[ni][k & 1]        = fmaxf(cmv[ni][k & 1], a);
                }

        if (pf) CP_WAIT0();   // this thread's prefetch chunks landed
        __syncthreads();      // everyone done reading old buffer before overwrite

        // colmin flush AFTER the barrier: shfl-max + fire-and-forget RED.MIN
        #pragma unroll
        for (int ni = 0; ni < 4; ni++)
            #pragma unroll
            for (int e = 0; e < 2; e++) {
                float v = cmv[ni][e];
                v = fmaxf(v, __shfl_xor_sync(0xffffffffu, v, 4));
                v = fmaxf(v, __shfl_xor_sync(0xffffffffu, v, 8));
                v = fmaxf(v, __shfl_xor_sync(0xffffffffu, v, 16));
                if (ln < 4) {
                    float d2 = fmaxf(-2.0f * v, 0.0f);
                    atomicMin(&g_colmin[b * NPTS + t * 128 + wn * 32 + ni * 8 + ln * 2 + e],
                              __float_as_uint(d2));
                }
            }
    }

    // ---- final rowmin: fold cols across lanes, scale, clamp, RED.MIN ----
    #pragma unroll
    for (int r = 0; r < 8; r++) {
        float v = rm[r];
        v = fmaxf(v, __shfl_xor_sync(0xffffffffu, v, 1));
        v = fmaxf(v, __shfl_xor_sync(0xffffffffu, v, 2));
        if ((ln & 3) == 0) {
            int row = wm * 64 + (r >> 1) * 16 + (ln >> 2) + (r & 1) * 8;
            float d2 = fmaxf(-2.0f * v, 0.0f);
            atomicMin(&g_rowmin[b * NPTS + n0 + row], __float_as_uint(d2));
        }
    }

    // ---- fused finalize: last CTA reduces everything ----
    __threadfence();                       // make our REDs visible
    __shared__ unsigned s_last;
    if (tid == 0) s_last = (atomicAdd(&g_done, 1u) == GRID_MAIN - 1u) ? 1u : 0u;
    __syncthreads();
    if (s_last) {
        float* s_red = (float*)(sm + S_HY_OFF);   // reuse smem
        float sum = 0.0f;
        for (int bb = 0; bb < BATCH; bb++) {
            float mx = 0.0f;
            for (int i = tid; i < NPTS; i += 256) {
                mx = fmaxf(mx, __uint_as_float(g_rowmin[bb * NPTS + i]));
                mx = fmaxf(mx, __uint_as_float(g_colmin[bb * NPTS + i]));
            }
            s_red[tid] = mx;
            __syncthreads();
            for (int st = 128; st > 0; st >>= 1) {
                if (tid < st) s_red[tid] = fmaxf(s_red[tid], s_red[tid + st]);
                __syncthreads();
            }
            if (tid == 0) sum += sqrtf(s_red[0]);
            __syncthreads();
        }
        if (tid == 0) out[0] = sum * (1.0f / BATCH);
    }
}

// ---------------------------------------------------------------------------
extern "C" void kernel_launch(void* const* d_in, const int* in_sizes, int n_in,
                              void* d_out, int out_size) {
    const float* x = (const float*)d_in[0];
    const float* y = (const float*)d_in[1];
    float* out = (float*)d_out;

    (void)cudaFuncSetAttribute(hd_main, cudaFuncAttributeMaxDynamicSharedMemorySize,
                               SMEM_BYTES);

    // 32768 rows x 8 threads = 262144 threads -> 1024 CTAs
    hd_prep<<<1024, 256>>>(x, y);
    hd_main<<<GRID_MAIN, 256, SMEM_BYTES>>>(out);
}